// round 1
// baseline (speedup 1.0000x reference)
#include <cuda_runtime.h>
#include <math.h>
#include <stdint.h>

// ---------------------------------------------------------------------------
// Problem constants
// ---------------------------------------------------------------------------
#define Bsz 4
#define Nseq 2048
#define Dm 1024
#define Hm 2048
#define QKd 128
#define Gsz 256
#define ROWS (Bsz * Nseq)          // 8192
#define NGROUPS (Bsz * (Nseq/Gsz)) // 32

// scratch layout (floats)
#define OFF_NORMED 0ll                                   // 8192*1024
#define OFF_H      (OFF_NORMED + (long long)ROWS*Dm)     // 8192*4096
#define OFF_QK     (OFF_H + (long long)ROWS*2*Hm)        // 8192*128
#define OFF_HEADS  (OFF_QK + (long long)ROWS*QKd)        // 4*8192*128
#define OFF_ATTN   (OFF_HEADS + 4ll*ROWS*QKd)            // 32*256*256
#define OFF_QUAD   (OFF_ATTN + (long long)NGROUPS*Gsz*Gsz) // 8192*2048
#define OFF_LINKV  (OFF_QUAD + (long long)ROWS*Hm)       // 4*128*2048
#define SCRATCH_FLOATS (OFF_LINKV + (long long)Bsz*QKd*Hm)

__device__ float g_scratch[SCRATCH_FLOATS];   // 2^26 floats = 256 MiB

// ---------------------------------------------------------------------------
// LayerNorm: one block per row (D=1024), 256 threads, float4
// ---------------------------------------------------------------------------
__global__ void layernorm_kernel(const float* __restrict__ x,
                                 const float* __restrict__ g,
                                 const float* __restrict__ b,
                                 float* __restrict__ out) {
    long long row = blockIdx.x;
    int t = threadIdx.x;
    const float4* xr = (const float4*)(x + row * Dm);
    float4 v = xr[t];
    float s  = v.x + v.y + v.z + v.w;
    float sq = v.x*v.x + v.y*v.y + v.z*v.z + v.w*v.w;
    #pragma unroll
    for (int o = 16; o; o >>= 1) {
        s  += __shfl_xor_sync(0xffffffffu, s,  o);
        sq += __shfl_xor_sync(0xffffffffu, sq, o);
    }
    __shared__ float ss[8], sqs[8];
    if ((t & 31) == 0) { ss[t >> 5] = s; sqs[t >> 5] = sq; }
    __syncthreads();
    if (t < 32) {
        float a  = (t < 8) ? ss[t]  : 0.f;
        float a2 = (t < 8) ? sqs[t] : 0.f;
        #pragma unroll
        for (int o = 4; o; o >>= 1) {
            a  += __shfl_xor_sync(0xffffffffu, a,  o);
            a2 += __shfl_xor_sync(0xffffffffu, a2, o);
        }
        if (t == 0) { ss[0] = a; sqs[0] = a2; }
    }
    __syncthreads();
    float mean = ss[0] * (1.f / Dm);
    float var  = sqs[0] * (1.f / Dm) - mean * mean;
    float inv  = rsqrtf(var + 1e-5f);
    float4 gg = ((const float4*)g)[t];
    float4 bb = ((const float4*)b)[t];
    float4 o;
    o.x = (v.x - mean) * inv * gg.x + bb.x;
    o.y = (v.y - mean) * inv * gg.y + bb.y;
    o.z = (v.z - mean) * inv * gg.z + bb.z;
    o.w = (v.w - mean) * inv * gg.w + bb.w;
    ((float4*)(out + row * Dm))[t] = o;
}

// ---------------------------------------------------------------------------
// OffsetScale + RoPE. grid = 8192 rows, block = 256 (head = tid/64, j = tid%64)
// heads layout: [4][8192][128], head order: quad_q, lin_q, quad_k, lin_k
// ---------------------------------------------------------------------------
__global__ void rope_kernel(const float* __restrict__ qk,
                            const float* __restrict__ b_qk,
                            const float* __restrict__ gamma,
                            const float* __restrict__ beta,
                            float* __restrict__ heads) {
    int row = blockIdx.x;
    int h = threadIdx.x >> 6;
    int j = threadIdx.x & 63;
    __shared__ float s[QKd];
    __shared__ float sc[64], ss_[64];
    if (threadIdx.x < QKd) {
        float z = qk[(long long)row * QKd + threadIdx.x] + b_qk[threadIdx.x];
        s[threadIdx.x] = z / (1.f + expf(-z));
    }
    if (threadIdx.x < 64) {
        int pos = row & (Nseq - 1);
        float invf = powf(10000.0f, (float)threadIdx.x * (1.0f / 64.0f));
        float th = (float)pos * invf;          // fp32 product, like reference
        sc[threadIdx.x]  = cosf(th);
        ss_[threadIdx.x] = sinf(th);
    }
    __syncthreads();
    float a1 = s[j]      * gamma[h * QKd + j]      + beta[h * QKd + j];
    float a2 = s[j + 64] * gamma[h * QKd + j + 64] + beta[h * QKd + j + 64];
    float cs = sc[j], sn = ss_[j];
    long long base = ((long long)h * ROWS + row) * QKd;
    heads[base + j]      = a1 * cs - a2 * sn;
    heads[base + j + 64] = a2 * cs + a1 * sn;
}

// ---------------------------------------------------------------------------
// Generic tiled SGEMM, 128x128x16, 256 threads, 8x8 per thread.
// C[m,n] = scale * sum_k A(m,k) * B(k,n)  (+ epilogue)
// TA: A stored [K,M] (lda = stride between k-rows). TB: B stored [N,K].
// grid.z = batches * nk (split-K chunks). All dims multiples of tiles.
// ---------------------------------------------------------------------------
#define BM 128
#define BN 128
#define BK 16
#define TM 8
#define TN 8

#define EPI_STORE   0
#define EPI_SILU    1
#define EPI_RELU2   2
#define EPI_ATOMIC  3
#define EPI_COMBINE 4   // C = ep0 * (ep1 + acc)
#define EPI_FINAL   5   // C = acc + bias + ep0

template<int EPI, bool TA, bool TB>
__global__ void gemm_kernel(const float* __restrict__ A,
                            const float* __restrict__ B,
                            float* __restrict__ C,
                            int M, int N, int K_total,
                            int lda, int ldb, int ldc,
                            long long sA, long long sB, long long sC,
                            int nk, float scale,
                            const float* __restrict__ bias,
                            const float* __restrict__ ep0, long long s0, int ld0,
                            const float* __restrict__ ep1, long long s1, int ld1) {
    int z = blockIdx.z;
    int batch = z / nk, kc = z % nk;
    int kchunk = K_total / nk;
    A += batch * sA; B += batch * sB; C += batch * sC;
    if (ep0) ep0 += batch * s0;
    if (ep1) ep1 += batch * s1;
    if (TA) A += (long long)kc * kchunk * lda; else A += (long long)kc * kchunk;
    if (TB) B += (long long)kc * kchunk;       else B += (long long)kc * kchunk * ldb;

    __shared__ float As[BK][BM];
    __shared__ float Bs[BK][BN];
    int tid = threadIdx.x;
    int tx = tid & 15, ty = tid >> 4;
    int m0 = blockIdx.y * BM, n0 = blockIdx.x * BN;

    float acc[TM][TN];
    #pragma unroll
    for (int i = 0; i < TM; i++)
        #pragma unroll
        for (int j = 0; j < TN; j++) acc[i][j] = 0.f;

    for (int k0 = 0; k0 < kchunk; k0 += BK) {
        if (!TA) {
            #pragma unroll
            for (int i = 0; i < 2; i++) {
                int f = tid + i * 256;
                int r = f >> 2;
                int c4 = (f & 3) * 4;
                float4 v = *(const float4*)(A + (long long)(m0 + r) * lda + k0 + c4);
                As[c4 + 0][r] = v.x; As[c4 + 1][r] = v.y;
                As[c4 + 2][r] = v.z; As[c4 + 3][r] = v.w;
            }
        } else {
            #pragma unroll
            for (int i = 0; i < 2; i++) {
                int f = tid + i * 256;
                int r = f >> 5;
                int c4 = (f & 31) * 4;
                float4 v = *(const float4*)(A + (long long)(k0 + r) * lda + m0 + c4);
                *(float4*)&As[r][c4] = v;
            }
        }
        if (!TB) {
            #pragma unroll
            for (int i = 0; i < 2; i++) {
                int f = tid + i * 256;
                int r = f >> 5;
                int c4 = (f & 31) * 4;
                float4 v = *(const float4*)(B + (long long)(k0 + r) * ldb + n0 + c4);
                *(float4*)&Bs[r][c4] = v;
            }
        } else {
            #pragma unroll
            for (int i = 0; i < 8; i++) {
                int f = tid + i * 256;
                int nn = f >> 4;
                int kk = f & 15;
                Bs[kk][nn] = B[(long long)(n0 + nn) * ldb + k0 + kk];
            }
        }
        __syncthreads();
        #pragma unroll
        for (int kk = 0; kk < BK; kk++) {
            float a[TM], bb[TN];
            #pragma unroll
            for (int i = 0; i < TM; i++) a[i] = As[kk][ty * TM + i];
            #pragma unroll
            for (int j = 0; j < TN; j++) bb[j] = Bs[kk][tx * TN + j];
            #pragma unroll
            for (int i = 0; i < TM; i++)
                #pragma unroll
                for (int j = 0; j < TN; j++)
                    acc[i][j] += a[i] * bb[j];
        }
        __syncthreads();
    }

    #pragma unroll
    for (int i = 0; i < TM; i++) {
        int row = m0 + ty * TM + i;
        #pragma unroll
        for (int j = 0; j < TN; j++) {
            int col = n0 + tx * TN + j;
            float v = acc[i][j] * scale;
            if (bias) v += bias[col];
            long long idx = (long long)row * ldc + col;
            if (EPI == EPI_STORE) {
                C[idx] = v;
            } else if (EPI == EPI_SILU) {
                C[idx] = v / (1.f + expf(-v));
            } else if (EPI == EPI_RELU2) {
                float r = v > 0.f ? v : 0.f;
                C[idx] = r * r;
            } else if (EPI == EPI_ATOMIC) {
                atomicAdd(&C[idx], v);
            } else if (EPI == EPI_COMBINE) {
                C[idx] = ep0[(long long)row * ld0 + col] *
                         (ep1[(long long)row * ld1 + col] + v);
            } else if (EPI == EPI_FINAL) {
                C[idx] = v + ep0[(long long)row * ld0 + col];
            }
        }
    }
}

// ---------------------------------------------------------------------------
// launch
// ---------------------------------------------------------------------------
extern "C" void kernel_launch(void* const* d_in, const int* in_sizes, int n_in,
                              void* d_out, int out_size) {
    const float* x        = (const float*)d_in[0];
    const float* ln_g     = (const float*)d_in[1];
    const float* ln_b     = (const float*)d_in[2];
    const float* W_hidden = (const float*)d_in[3];
    const float* b_hidden = (const float*)d_in[4];
    const float* W_qk     = (const float*)d_in[5];
    const float* b_qk     = (const float*)d_in[6];
    const float* os_gamma = (const float*)d_in[7];
    const float* os_beta  = (const float*)d_in[8];
    const float* W_out    = (const float*)d_in[9];
    const float* b_out    = (const float*)d_in[10];
    float* out = (float*)d_out;

    float* S = nullptr;
    cudaGetSymbolAddress((void**)&S, g_scratch);
    float* normed = S + OFF_NORMED;
    float* hbuf   = S + OFF_H;       // [8192, 4096]; v = cols [0,2048), gate = cols [2048,4096)
    float* qk     = S + OFF_QK;      // [8192, 128]
    float* heads  = S + OFF_HEADS;   // [4][8192][128]
    float* attn   = S + OFF_ATTN;    // [32][256][256]
    float* quad   = S + OFF_QUAD;    // [8192, 2048] (quad_out, then combined pre-out)
    float* linkv  = S + OFF_LINKV;   // [4][128][2048]

    const long long HEAD_SZ = (long long)ROWS * QKd;

    // 1) LayerNorm
    layernorm_kernel<<<ROWS, 256>>>(x, ln_g, ln_b, normed);

    // zero split-K accumulators
    cudaMemsetAsync(qk,    0, (size_t)ROWS * QKd * sizeof(float), 0);
    cudaMemsetAsync(linkv, 0, (size_t)Bsz * QKd * Hm * sizeof(float), 0);

    // 2) hidden GEMM + bias + silu : h = silu(normed @ W_hidden + b_hidden)
    gemm_kernel<EPI_SILU, false, false><<<dim3(2 * Hm / BN, ROWS / BM, 1), 256>>>(
        normed, W_hidden, hbuf, ROWS, 2 * Hm, Dm, Dm, 2 * Hm, 2 * Hm,
        0, 0, 0, 1, 1.f, b_hidden, nullptr, 0, 0, nullptr, 0, 0);

    // 3) qk GEMM (split-K=4, atomic accumulate; bias+silu folded into rope kernel)
    gemm_kernel<EPI_ATOMIC, false, false><<<dim3(1, ROWS / BM, 4), 256>>>(
        normed, W_qk, qk, ROWS, QKd, Dm, Dm, QKd, QKd,
        0, 0, 0, 4, 1.f, nullptr, nullptr, 0, 0, nullptr, 0, 0);

    // 4) OffsetScale + RoPE -> 4 head tensors
    rope_kernel<<<ROWS, 256>>>(qk, b_qk, os_gamma, os_beta, heads);

    // 5) group scores: attn = relu(QqKq^T / g)^2   (32 groups of 256x256x128)
    gemm_kernel<EPI_RELU2, false, true><<<dim3(2, 2, NGROUPS), 256>>>(
        heads + 0 * HEAD_SZ, heads + 2 * HEAD_SZ, attn, Gsz, Gsz, QKd,
        QKd, QKd, Gsz,
        (long long)Gsz * QKd, (long long)Gsz * QKd, (long long)Gsz * Gsz,
        1, 1.f / Gsz, nullptr, nullptr, 0, 0, nullptr, 0, 0);

    // 6) quad_out = attn @ v   (per group, v = hbuf cols [0,2048))
    gemm_kernel<EPI_STORE, false, false><<<dim3(Hm / BN, 2, NGROUPS), 256>>>(
        attn, hbuf, quad, Gsz, Hm, Gsz, Gsz, 2 * Hm, Hm,
        (long long)Gsz * Gsz, (long long)Gsz * 2 * Hm, (long long)Gsz * Hm,
        1, 1.f, nullptr, nullptr, 0, 0, nullptr, 0, 0);

    // 7) lin_kv = (lin_k^T @ v) / N   (per batch, split-K=8, atomic)
    gemm_kernel<EPI_ATOMIC, true, false><<<dim3(Hm / BN, 1, Bsz * 8), 256>>>(
        heads + 3 * HEAD_SZ, hbuf, linkv, QKd, Hm, Nseq, QKd, 2 * Hm, Hm,
        (long long)Nseq * QKd, (long long)Nseq * 2 * Hm, (long long)QKd * Hm,
        8, 1.f / Nseq, nullptr, nullptr, 0, 0, nullptr, 0, 0);

    // 8) combine: pre = gate * (quad + lin_q @ lin_kv)   (per batch, in place on quad)
    gemm_kernel<EPI_COMBINE, false, false><<<dim3(Hm / BN, Nseq / BM, Bsz), 256>>>(
        heads + 1 * HEAD_SZ, linkv, quad, Nseq, Hm, QKd, QKd, Hm, Hm,
        (long long)Nseq * QKd, (long long)QKd * Hm, (long long)Nseq * Hm,
        1, 1.f, nullptr,
        hbuf + Hm, (long long)Nseq * 2 * Hm, 2 * Hm,      // gate
        quad,      (long long)Nseq * Hm,     Hm);         // quad_out

    // 9) final GEMM + b_out + residual x
    gemm_kernel<EPI_FINAL, false, false><<<dim3(Dm / BN, ROWS / BM, 1), 256>>>(
        quad, W_out, out, ROWS, Dm, Hm, Hm, Dm, Dm,
        0, 0, 0, 1, 1.f, b_out,
        x, 0, Dm, nullptr, 0, 0);
}

// round 2
// speedup vs baseline: 5.5085x; 5.5085x over previous
#include <cuda_runtime.h>
#include <cuda_bf16.h>
#include <math.h>
#include <stdint.h>

// ---------------------------------------------------------------------------
// Problem constants
// ---------------------------------------------------------------------------
#define Bsz 4
#define Nseq 2048
#define Dm 1024
#define Hm 2048
#define QKd 128
#define Gsz 256
#define ROWS (Bsz * Nseq)          // 8192
#define NGROUPS (Bsz * (Nseq/Gsz)) // 32
#define HEADSZ ((long long)ROWS * QKd)   // elements per head tensor

typedef __nv_bfloat16 bf16;
typedef __nv_bfloat162 bf162;

// ---------------------------------------------------------------------------
// Scratch (bytes, 256-aligned offsets)
// ---------------------------------------------------------------------------
#define OFF_NORMED 0ull                              // bf16 [8192][1024]  16MB
#define OFF_WH     (OFF_NORMED + 16777216ull)        // bf16 [1024][4096]   8MB
#define OFF_WQK    (OFF_WH     + 8388608ull)         // bf16 [1024][128]
#define OFF_WOUT   (OFF_WQK    + 262144ull)          // bf16 [2048][1024]   4MB
#define OFF_HBUF   (OFF_WOUT   + 4194304ull)         // bf16 [8192][4096]  64MB (v | gate)
#define OFF_QKF    (OFF_HBUF   + 67108864ull)        // f32  [8192][128]    4MB
#define OFF_HEADS  (OFF_QKF    + 4194304ull)         // bf16 [4][8192][128] 8MB
#define OFF_LINKT  (OFF_HEADS  + 8388608ull)         // bf16 [4][128][2048] 2MB
#define OFF_ATTN   (OFF_LINKT  + 2097152ull)         // bf16 [32][256][256] 4MB
#define OFF_QUAD   (OFF_ATTN   + 4194304ull)         // bf16 [8192][2048]  32MB
#define OFF_LKVF   (OFF_QUAD   + 33554432ull)        // f32  [4][128][2048] 4MB
#define OFF_LKVB   (OFF_LKVF   + 4194304ull)         // bf16 [4][128][2048] 2MB
#define OFF_COMB   (OFF_LKVB   + 2097152ull)         // bf16 [8192][2048]  32MB
#define SCR_BYTES  (OFF_COMB   + 33554432ull)

__device__ __align__(256) unsigned char g_scr[SCR_BYTES];

// ---------------------------------------------------------------------------
// PTX helpers
// ---------------------------------------------------------------------------
__device__ __forceinline__ void cpasync16(void* s, const void* g) {
    uint32_t sa = (uint32_t)__cvta_generic_to_shared(s);
    asm volatile("cp.async.cg.shared.global [%0], [%1], 16;\n" :: "r"(sa), "l"(g));
}
__device__ __forceinline__ void cp_commit() { asm volatile("cp.async.commit_group;\n"); }
__device__ __forceinline__ void cp_wait_all() { asm volatile("cp.async.wait_group 0;\n" ::: "memory"); }

__device__ __forceinline__ void ldsm4(uint32_t r[4], const void* p) {
    uint32_t a = (uint32_t)__cvta_generic_to_shared(p);
    asm volatile("ldmatrix.sync.aligned.m8n8.x4.shared.b16 {%0,%1,%2,%3}, [%4];\n"
                 : "=r"(r[0]), "=r"(r[1]), "=r"(r[2]), "=r"(r[3]) : "r"(a));
}
__device__ __forceinline__ void ldsm4t(uint32_t r[4], const void* p) {
    uint32_t a = (uint32_t)__cvta_generic_to_shared(p);
    asm volatile("ldmatrix.sync.aligned.m8n8.x4.trans.shared.b16 {%0,%1,%2,%3}, [%4];\n"
                 : "=r"(r[0]), "=r"(r[1]), "=r"(r[2]), "=r"(r[3]) : "r"(a));
}
__device__ __forceinline__ void mma16816(float c[4], const uint32_t a[4], uint32_t b0, uint32_t b1) {
    asm volatile("mma.sync.aligned.m16n8k16.row.col.f32.bf16.bf16.f32 "
                 "{%0,%1,%2,%3}, {%4,%5,%6,%7}, {%8,%9}, {%0,%1,%2,%3};\n"
                 : "+f"(c[0]), "+f"(c[1]), "+f"(c[2]), "+f"(c[3])
                 : "r"(a[0]), "r"(a[1]), "r"(a[2]), "r"(a[3]), "r"(b0), "r"(b1));
}

// ---------------------------------------------------------------------------
// LayerNorm (fp32 in, bf16 out)
// ---------------------------------------------------------------------------
__global__ void layernorm_kernel(const float* __restrict__ x,
                                 const float* __restrict__ g,
                                 const float* __restrict__ b,
                                 bf16* __restrict__ out) {
    long long row = blockIdx.x;
    int t = threadIdx.x;
    float4 v = ((const float4*)(x + row * Dm))[t];
    float s  = v.x + v.y + v.z + v.w;
    float sq = v.x*v.x + v.y*v.y + v.z*v.z + v.w*v.w;
    #pragma unroll
    for (int o = 16; o; o >>= 1) {
        s  += __shfl_xor_sync(0xffffffffu, s,  o);
        sq += __shfl_xor_sync(0xffffffffu, sq, o);
    }
    __shared__ float ss[8], sqs[8];
    if ((t & 31) == 0) { ss[t >> 5] = s; sqs[t >> 5] = sq; }
    __syncthreads();
    if (t < 32) {
        float a  = (t < 8) ? ss[t]  : 0.f;
        float a2 = (t < 8) ? sqs[t] : 0.f;
        #pragma unroll
        for (int o = 4; o; o >>= 1) {
            a  += __shfl_xor_sync(0xffffffffu, a,  o);
            a2 += __shfl_xor_sync(0xffffffffu, a2, o);
        }
        if (t == 0) { ss[0] = a; sqs[0] = a2; }
    }
    __syncthreads();
    float mean = ss[0] * (1.f / Dm);
    float var  = sqs[0] * (1.f / Dm) - mean * mean;
    float inv  = rsqrtf(var + 1e-5f);
    float4 gg = ((const float4*)g)[t];
    float4 bb = ((const float4*)b)[t];
    float o0 = (v.x - mean) * inv * gg.x + bb.x;
    float o1 = (v.y - mean) * inv * gg.y + bb.y;
    float o2 = (v.z - mean) * inv * gg.z + bb.z;
    float o3 = (v.w - mean) * inv * gg.w + bb.w;
    bf162* op = (bf162*)(out + row * Dm);
    op[2*t]   = __floats2bfloat162_rn(o0, o1);
    op[2*t+1] = __floats2bfloat162_rn(o2, o3);
}

// ---------------------------------------------------------------------------
// fp32 -> bf16 (vectorized by 4)
// ---------------------------------------------------------------------------
__global__ void f2bf_kernel(const float* __restrict__ in, bf16* __restrict__ out, int n4) {
    int i = blockIdx.x * blockDim.x + threadIdx.x;
    if (i < n4) {
        float4 v = ((const float4*)in)[i];
        ((bf162*)out)[2*i]   = __floats2bfloat162_rn(v.x, v.y);
        ((bf162*)out)[2*i+1] = __floats2bfloat162_rn(v.z, v.w);
    }
}

// ---------------------------------------------------------------------------
// OffsetScale + RoPE (fp32 math; bf16 out). Also writes lin_k transposed.
// heads: [4][8192][128]; linkT: [4 batches][128][2048]
// ---------------------------------------------------------------------------
__global__ void rope_kernel(const float* __restrict__ qk,
                            const float* __restrict__ b_qk,
                            const float* __restrict__ gamma,
                            const float* __restrict__ beta,
                            bf16* __restrict__ heads,
                            bf16* __restrict__ linkT) {
    int row = blockIdx.x;
    int h = threadIdx.x >> 6;
    int j = threadIdx.x & 63;
    __shared__ float s[QKd];
    __shared__ float sc[64], ss_[64];
    if (threadIdx.x < QKd) {
        float z = qk[(long long)row * QKd + threadIdx.x] + b_qk[threadIdx.x];
        s[threadIdx.x] = z / (1.f + expf(-z));
    }
    if (threadIdx.x < 64) {
        int pos = row & (Nseq - 1);
        float invf = powf(10000.0f, (float)threadIdx.x * (1.0f / 64.0f));
        float th = (float)pos * invf;
        sc[threadIdx.x]  = cosf(th);
        ss_[threadIdx.x] = sinf(th);
    }
    __syncthreads();
    float a1 = s[j]      * gamma[h * QKd + j]      + beta[h * QKd + j];
    float a2 = s[j + 64] * gamma[h * QKd + j + 64] + beta[h * QKd + j + 64];
    float cs = sc[j], sn = ss_[j];
    float r1 = a1 * cs - a2 * sn;
    float r2 = a2 * cs + a1 * sn;
    long long base = ((long long)h * ROWS + row) * QKd;
    heads[base + j]      = __float2bfloat16_rn(r1);
    heads[base + j + 64] = __float2bfloat16_rn(r2);
    if (h == 3) {
        int batch = row >> 11;           // /2048
        int pos   = row & (Nseq - 1);
        long long tb = (long long)batch * QKd * Nseq;
        linkT[tb + (long long)j * Nseq + pos]        = __float2bfloat16_rn(r1);
        linkT[tb + (long long)(j + 64) * Nseq + pos] = __float2bfloat16_rn(r2);
    }
}

// ---------------------------------------------------------------------------
// bf16 tensor-core GEMM: 128x128x32 block, 8 warps (4x2), 32x64 warp tiles.
// A row-major [M][K]. BL=0: B stored [K][N]; BL=1: B stored [N][K].
// ---------------------------------------------------------------------------
#define BM 128
#define BN 128
#define BK 32

#define EPI_SILU    0
#define EPI_RELU2   1
#define EPI_STOREB  2
#define EPI_ATOMIC  3
#define EPI_COMBINE 4
#define EPI_FINAL   5

template<int EPI, int BL>
__global__ __launch_bounds__(256)
void gemm_bf16(const bf16* __restrict__ A, const bf16* __restrict__ B,
               void* __restrict__ Cv,
               int lda, int ldb, int ldc,
               int kchunk, int nk,
               long long sA, long long sB, long long sC,
               float scale,
               const float* __restrict__ bias,
               const bf16* __restrict__ ep0, long long s0, int ld0,
               const bf16* __restrict__ ep1, long long s1, int ld1,
               const float* __restrict__ xres, int ldx) {
    const int tid = threadIdx.x;
    const int z = blockIdx.z;
    const int batch = z / nk, kc = z - batch * nk;
    A += batch * sA + (long long)kc * kchunk;
    if (BL == 0) B += batch * sB + (long long)kc * kchunk * ldb;
    else         B += batch * sB + (long long)kc * kchunk;
    const int m0 = blockIdx.y * BM, n0 = blockIdx.x * BN;

    constexpr int LDA_S = BK + 8;                       // 40
    constexpr int LDB_S = (BL == 0) ? (BN + 8) : (BK + 8);
    constexpr int BS_ELEMS = (BL == 0) ? BK * (BN + 8) : BN * (BK + 8);
    __shared__ __align__(16) bf16 As[2][BM * LDA_S];
    __shared__ __align__(16) bf16 Bs[2][BS_ELEMS];

    const int lane = tid & 31, wid = tid >> 5;
    const int wm = wid & 3, wn = wid >> 2;

    // global->smem mapping
    const int ar  = tid >> 2, ac  = (tid & 3) * 8;      // A rows 0..63 (+64)
    const int b0r = tid >> 4, b0c = (tid & 15) * 8;     // BL0: k rows 0..15 (+16)
    const int b1r = tid >> 2, b1c = (tid & 3) * 8;      // BL1: n rows 0..63 (+64)

    float acc[2][8][4];
    #pragma unroll
    for (int i = 0; i < 2; i++)
        #pragma unroll
        for (int j = 0; j < 8; j++)
            #pragma unroll
            for (int q = 0; q < 4; q++) acc[i][j][q] = 0.f;

    const int iters = kchunk / BK;

    auto load_tiles = [&](int buf, int k) {
        const bf16* ga = A + (long long)(m0 + ar) * lda + k + ac;
        cpasync16(&As[buf][ar * LDA_S + ac], ga);
        cpasync16(&As[buf][(ar + 64) * LDA_S + ac], ga + 64ll * lda);
        if (BL == 0) {
            const bf16* gb = B + (long long)(k + b0r) * ldb + n0 + b0c;
            cpasync16(&Bs[buf][b0r * LDB_S + b0c], gb);
            cpasync16(&Bs[buf][(b0r + 16) * LDB_S + b0c], gb + 16ll * ldb);
        } else {
            const bf16* gb = B + (long long)(n0 + b1r) * ldb + k + b1c;
            cpasync16(&Bs[buf][b1r * LDB_S + b1c], gb);
            cpasync16(&Bs[buf][(b1r + 64) * LDB_S + b1c], gb + 64ll * ldb);
        }
    };

    load_tiles(0, 0);
    cp_commit();

    for (int it = 0; it < iters; ++it) {
        cp_wait_all();
        __syncthreads();
        if (it + 1 < iters) { load_tiles((it + 1) & 1, (it + 1) * BK); cp_commit(); }
        const int buf = it & 1;
        #pragma unroll
        for (int ks = 0; ks < 2; ++ks) {
            uint32_t a[2][4];
            #pragma unroll
            for (int mi = 0; mi < 2; ++mi)
                ldsm4(a[mi], &As[buf][(wm * 32 + mi * 16 + (lane & 15)) * LDA_S +
                                      ks * 16 + (lane >> 4) * 8]);
            uint32_t b[4][4];
            #pragma unroll
            for (int nb = 0; nb < 4; ++nb) {
                if (BL == 0)
                    ldsm4t(b[nb], &Bs[buf][(ks * 16 + (lane & 15)) * LDB_S +
                                           wn * 64 + nb * 16 + (lane >> 4) * 8]);
                else
                    ldsm4(b[nb], &Bs[buf][(wn * 64 + nb * 16 + (lane & 7) + (lane >> 4) * 8) * LDB_S +
                                          ks * 16 + ((lane >> 3) & 1) * 8]);
            }
            #pragma unroll
            for (int mi = 0; mi < 2; ++mi)
                #pragma unroll
                for (int nb = 0; nb < 4; ++nb) {
                    mma16816(acc[mi][2 * nb],     a[mi], b[nb][0], b[nb][1]);
                    mma16816(acc[mi][2 * nb + 1], a[mi], b[nb][2], b[nb][3]);
                }
        }
        __syncthreads();
    }

    // epilogue
    #pragma unroll
    for (int mi = 0; mi < 2; ++mi)
        #pragma unroll
        for (int r2 = 0; r2 < 2; ++r2) {
            int row = m0 + wm * 32 + mi * 16 + (lane >> 2) + r2 * 8;
            #pragma unroll
            for (int nb = 0; nb < 8; ++nb) {
                int col = n0 + wn * 64 + nb * 8 + (lane & 3) * 2;
                float v0 = acc[mi][nb][r2 * 2]     * scale;
                float v1 = acc[mi][nb][r2 * 2 + 1] * scale;
                long long idx = batch * sC + (long long)row * ldc + col;
                if (EPI == EPI_SILU) {
                    v0 += bias[col]; v1 += bias[col + 1];
                    v0 = v0 / (1.f + expf(-v0));
                    v1 = v1 / (1.f + expf(-v1));
                    *(bf162*)((bf16*)Cv + idx) = __floats2bfloat162_rn(v0, v1);
                } else if (EPI == EPI_RELU2) {
                    float r0 = v0 > 0.f ? v0 : 0.f;
                    float r1 = v1 > 0.f ? v1 : 0.f;
                    *(bf162*)((bf16*)Cv + idx) = __floats2bfloat162_rn(r0 * r0, r1 * r1);
                } else if (EPI == EPI_STOREB) {
                    *(bf162*)((bf16*)Cv + idx) = __floats2bfloat162_rn(v0, v1);
                } else if (EPI == EPI_ATOMIC) {
                    atomicAdd((float*)Cv + idx, v0);
                    atomicAdd((float*)Cv + idx + 1, v1);
                } else if (EPI == EPI_COMBINE) {
                    bf162 g2 = *(const bf162*)(ep0 + batch * s0 + (long long)row * ld0 + col);
                    bf162 q2 = *(const bf162*)(ep1 + batch * s1 + (long long)row * ld1 + col);
                    float o0 = __bfloat162float(g2.x) * (__bfloat162float(q2.x) + v0);
                    float o1 = __bfloat162float(g2.y) * (__bfloat162float(q2.y) + v1);
                    *(bf162*)((bf16*)Cv + idx) = __floats2bfloat162_rn(o0, o1);
                } else if (EPI == EPI_FINAL) {
                    v0 += bias[col] + xres[(long long)row * ldx + col];
                    v1 += bias[col + 1] + xres[(long long)row * ldx + col + 1];
                    *(float2*)((float*)Cv + idx) = make_float2(v0, v1);
                }
            }
        }
}

// ---------------------------------------------------------------------------
// launch
// ---------------------------------------------------------------------------
extern "C" void kernel_launch(void* const* d_in, const int* in_sizes, int n_in,
                              void* d_out, int out_size) {
    const float* x        = (const float*)d_in[0];
    const float* ln_g     = (const float*)d_in[1];
    const float* ln_b     = (const float*)d_in[2];
    const float* W_hidden = (const float*)d_in[3];
    const float* b_hidden = (const float*)d_in[4];
    const float* W_qk     = (const float*)d_in[5];
    const float* b_qk     = (const float*)d_in[6];
    const float* os_gamma = (const float*)d_in[7];
    const float* os_beta  = (const float*)d_in[8];
    const float* W_out    = (const float*)d_in[9];
    const float* b_out    = (const float*)d_in[10];
    float* out = (float*)d_out;

    unsigned char* S = nullptr;
    cudaGetSymbolAddress((void**)&S, g_scr);
    bf16*  normed = (bf16*)(S + OFF_NORMED);
    bf16*  Wh     = (bf16*)(S + OFF_WH);
    bf16*  Wqk    = (bf16*)(S + OFF_WQK);
    bf16*  Wout   = (bf16*)(S + OFF_WOUT);
    bf16*  hbuf   = (bf16*)(S + OFF_HBUF);    // [8192][4096]: v | gate
    float* qkf    = (float*)(S + OFF_QKF);
    bf16*  heads  = (bf16*)(S + OFF_HEADS);
    bf16*  linkT  = (bf16*)(S + OFF_LINKT);
    bf16*  attn   = (bf16*)(S + OFF_ATTN);
    bf16*  quad   = (bf16*)(S + OFF_QUAD);
    float* lkvf   = (float*)(S + OFF_LKVF);
    bf16*  lkvb   = (bf16*)(S + OFF_LKVB);
    bf16*  comb   = (bf16*)(S + OFF_COMB);

    // weight conversions
    f2bf_kernel<<<(Dm * 2 * Hm / 4 + 255) / 256, 256>>>(W_hidden, Wh, Dm * 2 * Hm / 4);
    f2bf_kernel<<<(Dm * QKd / 4 + 255) / 256, 256>>>(W_qk, Wqk, Dm * QKd / 4);
    f2bf_kernel<<<(Hm * Dm / 4 + 255) / 256, 256>>>(W_out, Wout, Hm * Dm / 4);

    // LayerNorm -> bf16
    layernorm_kernel<<<ROWS, 256>>>(x, ln_g, ln_b, normed);

    // zero split-K accumulators
    cudaMemsetAsync(qkf,  0, (size_t)ROWS * QKd * sizeof(float), 0);
    cudaMemsetAsync(lkvf, 0, (size_t)Bsz * QKd * Hm * sizeof(float), 0);

    // 2) hidden: hbuf = silu(normed @ W_hidden + b_hidden)   [8192 x 4096 x 1024]
    gemm_bf16<EPI_SILU, 0><<<dim3(2 * Hm / BN, ROWS / BM, 1), 256>>>(
        normed, Wh, hbuf, Dm, 2 * Hm, 2 * Hm, Dm, 1, 0, 0, 0, 1.f,
        b_hidden, nullptr, 0, 0, nullptr, 0, 0, nullptr, 0);

    // 3) qk = normed @ W_qk  (split-K=4, fp32 atomics)       [8192 x 128 x 1024]
    gemm_bf16<EPI_ATOMIC, 0><<<dim3(1, ROWS / BM, 4), 256>>>(
        normed, Wqk, qkf, Dm, QKd, QKd, Dm / 4, 4, 0, 0, 0, 1.f,
        nullptr, nullptr, 0, 0, nullptr, 0, 0, nullptr, 0);

    // 4) OffsetScale + RoPE
    rope_kernel<<<ROWS, 256>>>(qkf, b_qk, os_gamma, os_beta, heads, linkT);

    // 5) attn = relu(QqKq^T / G)^2   per group               [256 x 256 x 128] x32
    gemm_bf16<EPI_RELU2, 1><<<dim3(2, 2, NGROUPS), 256>>>(
        heads + 0 * HEADSZ, heads + 2 * HEADSZ, attn, QKd, QKd, Gsz, QKd, 1,
        (long long)Gsz * QKd, (long long)Gsz * QKd, (long long)Gsz * Gsz, 1.f / Gsz,
        nullptr, nullptr, 0, 0, nullptr, 0, 0, nullptr, 0);

    // 6) quad = attn @ v   per group                          [256 x 2048 x 256] x32
    gemm_bf16<EPI_STOREB, 0><<<dim3(Hm / BN, 2, NGROUPS), 256>>>(
        attn, hbuf, quad, Gsz, 2 * Hm, Hm, Gsz, 1,
        (long long)Gsz * Gsz, (long long)Gsz * 2 * Hm, (long long)Gsz * Hm, 1.f,
        nullptr, nullptr, 0, 0, nullptr, 0, 0, nullptr, 0);

    // 7) lin_kv = (lin_k^T @ v) / N   per batch, split-K=4    [128 x 2048 x 2048] x4
    gemm_bf16<EPI_ATOMIC, 0><<<dim3(Hm / BN, 1, Bsz * 4), 256>>>(
        linkT, hbuf, lkvf, Nseq, 2 * Hm, Hm, Nseq / 4, 4,
        (long long)QKd * Nseq, (long long)Nseq * 2 * Hm, (long long)QKd * Hm, 1.f / Nseq,
        nullptr, nullptr, 0, 0, nullptr, 0, 0, nullptr, 0);
    f2bf_kernel<<<(Bsz * QKd * Hm / 4 + 255) / 256, 256>>>(lkvf, lkvb, Bsz * QKd * Hm / 4);

    // 8) comb = gate * (quad + lin_q @ lin_kv)  per batch     [2048 x 2048 x 128] x4
    gemm_bf16<EPI_COMBINE, 0><<<dim3(Hm / BN, Nseq / BM, Bsz), 256>>>(
        heads + 1 * HEADSZ, lkvb, comb, QKd, Hm, Hm, QKd, 1,
        (long long)Nseq * QKd, (long long)QKd * Hm, (long long)Nseq * Hm, 1.f,
        nullptr,
        hbuf + Hm, (long long)Nseq * 2 * Hm, 2 * Hm,    // gate
        quad,      (long long)Nseq * Hm,     Hm,        // quad_out
        nullptr, 0);

    // 9) out = comb @ W_out + b_out + x                       [8192 x 1024 x 2048]
    gemm_bf16<EPI_FINAL, 0><<<dim3(Dm / BN, ROWS / BM, 1), 256>>>(
        comb, Wout, out, Hm, Dm, Dm, Hm, 1, 0, 0, 0, 1.f,
        b_out, nullptr, 0, 0, nullptr, 0, 0, x, Dm);
}

// round 5
// speedup vs baseline: 5.7311x; 1.0404x over previous
#include <cuda_runtime.h>
#include <cuda_bf16.h>
#include <math.h>
#include <stdint.h>

// ---------------------------------------------------------------------------
// Problem constants
// ---------------------------------------------------------------------------
#define Bsz 4
#define Nseq 2048
#define Dm 1024
#define Hm 2048
#define QKd 128
#define Gsz 256
#define ROWS (Bsz * Nseq)          // 8192
#define NGROUPS (Bsz * (Nseq/Gsz)) // 32
#define HEADSZ ((long long)ROWS * QKd)

typedef __nv_bfloat16 bf16;
typedef __nv_bfloat162 bf162;

// ---------------------------------------------------------------------------
// Scratch (bytes)
// ---------------------------------------------------------------------------
#define OFF_NORMED 0ull                              // bf16 [8192][1024]  16MB
#define OFF_WH     (OFF_NORMED + 16777216ull)        // bf16 [1024][4096]   8MB
#define OFF_WQK    (OFF_WH     + 8388608ull)         // bf16 [1024][128]
#define OFF_WOUT   (OFF_WQK    + 262144ull)          // bf16 [2048][1024]   4MB
#define OFF_HBUF   (OFF_WOUT   + 4194304ull)         // bf16 [8192][4096]  64MB (v | gate)
#define OFF_QKF    (OFF_HBUF   + 67108864ull)        // f32  [8192][128]    4MB
#define OFF_HEADS  (OFF_QKF    + 4194304ull)         // bf16 [4][8192][128] 8MB
#define OFF_LINKT  (OFF_HEADS  + 8388608ull)         // bf16 [4][128][2048] 2MB
#define OFF_ATTN   (OFF_LINKT  + 2097152ull)         // bf16 [32][256][256] 4MB
#define OFF_QUAD   (OFF_ATTN   + 4194304ull)         // bf16 [8192][2048]  32MB
#define OFF_LKVF   (OFF_QUAD   + 33554432ull)        // f32  [4][128][2048] 4MB
#define OFF_LKVB   (OFF_LKVF   + 4194304ull)         // bf16 [4][128][2048] 2MB
#define OFF_COMB   (OFF_LKVB   + 2097152ull)         // bf16 [8192][2048]  32MB
#define SCR_BYTES  (OFF_COMB   + 33554432ull)

__device__ __align__(256) unsigned char g_scr[SCR_BYTES];

// ---------------------------------------------------------------------------
// PTX helpers
// ---------------------------------------------------------------------------
__device__ __forceinline__ uint32_t smem_u32(const void* p) {
    uint32_t a;
    asm("{ .reg .u64 t; cvta.to.shared.u64 t, %1; cvt.u32.u64 %0, t; }"
        : "=r"(a) : "l"(p));
    return a;
}
__device__ __forceinline__ void cpasync16(uint32_t s, const void* g) {
    asm volatile("cp.async.cg.shared.global [%0], [%1], 16;\n" :: "r"(s), "l"(g));
}
__device__ __forceinline__ void cp_commit() { asm volatile("cp.async.commit_group;\n"); }

__device__ __forceinline__ void ldsm4(uint32_t r[4], uint32_t a) {
    asm volatile("ldmatrix.sync.aligned.m8n8.x4.shared.b16 {%0,%1,%2,%3}, [%4];\n"
                 : "=r"(r[0]), "=r"(r[1]), "=r"(r[2]), "=r"(r[3]) : "r"(a));
}
__device__ __forceinline__ void ldsm4t(uint32_t r[4], uint32_t a) {
    asm volatile("ldmatrix.sync.aligned.m8n8.x4.trans.shared.b16 {%0,%1,%2,%3}, [%4];\n"
                 : "=r"(r[0]), "=r"(r[1]), "=r"(r[2]), "=r"(r[3]) : "r"(a));
}
__device__ __forceinline__ void mma16816(float c[4], const uint32_t a[4], uint32_t b0, uint32_t b1) {
    asm volatile("mma.sync.aligned.m16n8k16.row.col.f32.bf16.bf16.f32 "
                 "{%0,%1,%2,%3}, {%4,%5,%6,%7}, {%8,%9}, {%0,%1,%2,%3};\n"
                 : "+f"(c[0]), "+f"(c[1]), "+f"(c[2]), "+f"(c[3])
                 : "r"(a[0]), "r"(a[1]), "r"(a[2]), "r"(a[3]), "r"(b0), "r"(b1));
}

// Conflict-free swizzles.
// 64B rows (A tiles, [N][K] B tiles): 16B chunk index ^= (row>>1)&3
__device__ __forceinline__ uint32_t swz64(int r, int cb) {
    return (uint32_t)(r * 64 + ((((cb >> 4) ^ ((r >> 1) & 3)) << 4) | (cb & 15)));
}
// 256B rows ([K][N] B tiles): low 3 bits of 16B chunk index ^= k&7
__device__ __forceinline__ uint32_t swz256(int k, int nb) {
    int ch = nb >> 4;
    ch = (ch & 8) | ((ch ^ k) & 7);
    return (uint32_t)(k * 256 + (ch << 4) + (nb & 15));
}

// ---------------------------------------------------------------------------
// LayerNorm (fp32 in, bf16 out)
// ---------------------------------------------------------------------------
__global__ void layernorm_kernel(const float* __restrict__ x,
                                 const float* __restrict__ g,
                                 const float* __restrict__ b,
                                 bf16* __restrict__ out) {
    long long row = blockIdx.x;
    int t = threadIdx.x;
    float4 v = ((const float4*)(x + row * Dm))[t];
    float s  = v.x + v.y + v.z + v.w;
    float sq = v.x*v.x + v.y*v.y + v.z*v.z + v.w*v.w;
    #pragma unroll
    for (int o = 16; o; o >>= 1) {
        s  += __shfl_xor_sync(0xffffffffu, s,  o);
        sq += __shfl_xor_sync(0xffffffffu, sq, o);
    }
    __shared__ float ss[8], sqs[8];
    if ((t & 31) == 0) { ss[t >> 5] = s; sqs[t >> 5] = sq; }
    __syncthreads();
    if (t < 32) {
        float a  = (t < 8) ? ss[t]  : 0.f;
        float a2 = (t < 8) ? sqs[t] : 0.f;
        #pragma unroll
        for (int o = 4; o; o >>= 1) {
            a  += __shfl_xor_sync(0xffffffffu, a,  o);
            a2 += __shfl_xor_sync(0xffffffffu, a2, o);
        }
        if (t == 0) { ss[0] = a; sqs[0] = a2; }
    }
    __syncthreads();
    float mean = ss[0] * (1.f / Dm);
    float var  = sqs[0] * (1.f / Dm) - mean * mean;
    float inv  = rsqrtf(var + 1e-5f);
    float4 gg = ((const float4*)g)[t];
    float4 bb = ((const float4*)b)[t];
    bf162* op = (bf162*)(out + row * Dm);
    op[2*t]   = __floats2bfloat162_rn((v.x - mean) * inv * gg.x + bb.x,
                                      (v.y - mean) * inv * gg.y + bb.y);
    op[2*t+1] = __floats2bfloat162_rn((v.z - mean) * inv * gg.z + bb.z,
                                      (v.w - mean) * inv * gg.w + bb.w);
}

// ---------------------------------------------------------------------------
// fp32 -> bf16 (vectorized by 4)
// ---------------------------------------------------------------------------
__global__ void f2bf_kernel(const float* __restrict__ in, bf16* __restrict__ out, int n4) {
    int i = blockIdx.x * blockDim.x + threadIdx.x;
    if (i < n4) {
        float4 v = ((const float4*)in)[i];
        ((bf162*)out)[2*i]   = __floats2bfloat162_rn(v.x, v.y);
        ((bf162*)out)[2*i+1] = __floats2bfloat162_rn(v.z, v.w);
    }
}

// ---------------------------------------------------------------------------
// OffsetScale + RoPE (fp32 math; bf16 out). Also writes lin_k transposed.
// heads: [4][8192][128]; linkT: [4 batches][128][2048]
// ---------------------------------------------------------------------------
__global__ void rope_kernel(const float* __restrict__ qk,
                            const float* __restrict__ b_qk,
                            const float* __restrict__ gamma,
                            const float* __restrict__ beta,
                            bf16* __restrict__ heads,
                            bf16* __restrict__ linkT) {
    int row = blockIdx.x;
    int h = threadIdx.x >> 6;
    int j = threadIdx.x & 63;
    __shared__ float s[QKd];
    __shared__ float sc[64], ss_[64];
    if (threadIdx.x < QKd) {
        float z = qk[(long long)row * QKd + threadIdx.x] + b_qk[threadIdx.x];
        s[threadIdx.x] = z / (1.f + expf(-z));
    }
    if (threadIdx.x < 64) {
        int pos = row & (Nseq - 1);
        float invf = powf(10000.0f, (float)threadIdx.x * (1.0f / 64.0f));
        float th = (float)pos * invf;
        sc[threadIdx.x]  = cosf(th);
        ss_[threadIdx.x] = sinf(th);
    }
    __syncthreads();
    float a1 = s[j]      * gamma[h * QKd + j]      + beta[h * QKd + j];
    float a2 = s[j + 64] * gamma[h * QKd + j + 64] + beta[h * QKd + j + 64];
    float cs = sc[j], sn = ss_[j];
    float r1 = a1 * cs - a2 * sn;
    float r2 = a2 * cs + a1 * sn;
    long long base = ((long long)h * ROWS + row) * QKd;
    heads[base + j]      = __float2bfloat16_rn(r1);
    heads[base + j + 64] = __float2bfloat16_rn(r2);
    if (h == 3) {
        int batch = row >> 11;
        int pos   = row & (Nseq - 1);
        long long tb = (long long)batch * QKd * Nseq;
        linkT[tb + (long long)j * Nseq + pos]        = __float2bfloat16_rn(r1);
        linkT[tb + (long long)(j + 64) * Nseq + pos] = __float2bfloat16_rn(r2);
    }
}

// ---------------------------------------------------------------------------
// bf16 tensor-core GEMM: 128x128x32 block, 8 warps (4x2), 32x64 warp tiles.
// 3-stage cp.async pipeline, XOR-swizzled conflict-free smem.
// A row-major [M][K]. BL=0: B stored [K][N]; BL=1: B stored [N][K].
// ---------------------------------------------------------------------------
#define BM 128
#define BN 128
#define BK 32
#define STAGES 3
#define SMEM_BYTES (STAGES * 2 * 8192)     // 48KB

#define EPI_SILU    0
#define EPI_RELU2   1
#define EPI_STOREB  2
#define EPI_ATOMIC  3
#define EPI_COMBINE 4
#define EPI_FINAL   5

template<int EPI, int BL>
__global__ __launch_bounds__(256)
void gemm_bf16(const bf16* __restrict__ A, const bf16* __restrict__ B,
               void* __restrict__ Cv,
               int lda, int ldb, int ldc,
               int kchunk, int nk,
               long long sA, long long sB, long long sC,
               float scale,
               const float* __restrict__ bias,
               const bf16* __restrict__ ep0, long long s0, int ld0,
               const bf16* __restrict__ ep1, long long s1, int ld1,
               const float* __restrict__ xres, int ldx) {
    extern __shared__ unsigned char smem[];
    const uint32_t aSm = smem_u32(smem);                    // STAGES x 8KB
    const uint32_t bSm = aSm + STAGES * 8192;               // STAGES x 8KB

    const int tid = threadIdx.x;
    const int z = blockIdx.z;
    const int batch = z / nk, kc = z - batch * nk;
    A += batch * sA + (long long)kc * kchunk;
    if (BL == 0) B += batch * sB + (long long)kc * kchunk * ldb;
    else         B += batch * sB + (long long)kc * kchunk;
    const int m0 = blockIdx.y * BM, n0 = blockIdx.x * BN;

    const int lane = tid & 31, wid = tid >> 5;
    const int wm = wid & 3, wn = wid >> 2;

    float acc[2][8][4];
    #pragma unroll
    for (int i = 0; i < 2; i++)
        #pragma unroll
        for (int j = 0; j < 8; j++)
            #pragma unroll
            for (int q = 0; q < 4; q++) acc[i][j][q] = 0.f;

    const int iters = kchunk / BK;

    // global->smem mappings
    const int ar  = tid >> 2, acb = (tid & 3) * 16;   // A & BL1: rows 0..63(+64), 16B chunk
    const int b0k = tid >> 4, b0n = (tid & 15) * 16;  // BL0: k rows 0..15(+16)

    auto load_stage = [&](int st, int k0) {
        const uint32_t aDst = aSm + st * 8192;
        const bf16* ga = A + (long long)(m0 + ar) * lda + k0 + (acb >> 1);
        cpasync16(aDst + swz64(ar, acb), ga);
        cpasync16(aDst + swz64(ar + 64, acb), ga + 64ll * lda);
        const uint32_t bDst = bSm + st * 8192;
        if (BL == 0) {
            const bf16* gb = B + (long long)(k0 + b0k) * ldb + n0 + (b0n >> 1);
            cpasync16(bDst + swz256(b0k, b0n), gb);
            cpasync16(bDst + swz256(b0k + 16, b0n), gb + 16ll * ldb);
        } else {
            const bf16* gb = B + (long long)(n0 + ar) * ldb + k0 + (acb >> 1);
            cpasync16(bDst + swz64(ar, acb), gb);
            cpasync16(bDst + swz64(ar + 64, acb), gb + 64ll * ldb);
        }
        cp_commit();
    };

    load_stage(0, 0);
    if (iters > 1) load_stage(1, BK);

    for (int it = 0; it < iters; ++it) {
        if (it + 1 < iters) asm volatile("cp.async.wait_group 1;\n" ::: "memory");
        else                asm volatile("cp.async.wait_group 0;\n" ::: "memory");
        __syncthreads();
        if (it + 2 < iters) load_stage((it + 2) % STAGES, (it + 2) * BK);

        const int st = it % STAGES;
        const uint32_t aB = aSm + st * 8192;
        const uint32_t bB = bSm + st * 8192;
        #pragma unroll
        for (int ks = 0; ks < 2; ++ks) {
            uint32_t a[2][4];
            #pragma unroll
            for (int mi = 0; mi < 2; ++mi) {
                int r = wm * 32 + mi * 16 + (lane & 15);
                ldsm4(a[mi], aB + swz64(r, ks * 32 + (lane >> 4) * 16));
            }
            uint32_t b[4][4];
            #pragma unroll
            for (int nb = 0; nb < 4; ++nb) {
                if (BL == 0) {
                    int k = ks * 16 + (lane & 15);
                    int nbyte = (wn * 64 + nb * 16 + (lane >> 4) * 8) * 2;
                    ldsm4t(b[nb], bB + swz256(k, nbyte));
                } else {
                    int r = wn * 64 + nb * 16 + (lane & 7) + (lane >> 4) * 8;
                    int cb = (ks * 16 + ((lane >> 3) & 1) * 8) * 2;
                    ldsm4(b[nb], bB + swz64(r, cb));
                }
            }
            #pragma unroll
            for (int mi = 0; mi < 2; ++mi)
                #pragma unroll
                for (int nb = 0; nb < 4; ++nb) {
                    mma16816(acc[mi][2 * nb],     a[mi], b[nb][0], b[nb][1]);
                    mma16816(acc[mi][2 * nb + 1], a[mi], b[nb][2], b[nb][3]);
                }
        }
    }

    // epilogue
    #pragma unroll
    for (int mi = 0; mi < 2; ++mi)
        #pragma unroll
        for (int r2 = 0; r2 < 2; ++r2) {
            int row = m0 + wm * 32 + mi * 16 + (lane >> 2) + r2 * 8;
            #pragma unroll
            for (int nb = 0; nb < 8; ++nb) {
                int col = n0 + wn * 64 + nb * 8 + (lane & 3) * 2;
                float v0 = acc[mi][nb][r2 * 2]     * scale;
                float v1 = acc[mi][nb][r2 * 2 + 1] * scale;
                long long idx = batch * sC + (long long)row * ldc + col;
                if (EPI == EPI_SILU) {
                    v0 += bias[col]; v1 += bias[col + 1];
                    v0 = v0 / (1.f + expf(-v0));
                    v1 = v1 / (1.f + expf(-v1));
                    *(bf162*)((bf16*)Cv + idx) = __floats2bfloat162_rn(v0, v1);
                } else if (EPI == EPI_RELU2) {
                    float r0 = v0 > 0.f ? v0 : 0.f;
                    float r1 = v1 > 0.f ? v1 : 0.f;
                    *(bf162*)((bf16*)Cv + idx) = __floats2bfloat162_rn(r0 * r0, r1 * r1);
                } else if (EPI == EPI_STOREB) {
                    *(bf162*)((bf16*)Cv + idx) = __floats2bfloat162_rn(v0, v1);
                } else if (EPI == EPI_ATOMIC) {
                    atomicAdd((float*)Cv + idx, v0);
                    atomicAdd((float*)Cv + idx + 1, v1);
                } else if (EPI == EPI_COMBINE) {
                    bf162 g2 = *(const bf162*)(ep0 + batch * s0 + (long long)row * ld0 + col);
                    bf162 q2 = *(const bf162*)(ep1 + batch * s1 + (long long)row * ld1 + col);
                    float o0 = __bfloat162float(g2.x) * (__bfloat162float(q2.x) + v0);
                    float o1 = __bfloat162float(g2.y) * (__bfloat162float(q2.y) + v1);
                    *(bf162*)((bf16*)Cv + idx) = __floats2bfloat162_rn(o0, o1);
                } else if (EPI == EPI_FINAL) {
                    v0 += bias[col] + xres[(long long)row * ldx + col];
                    v1 += bias[col + 1] + xres[(long long)row * ldx + col + 1];
                    *(float2*)((float*)Cv + idx) = make_float2(v0, v1);
                }
            }
        }
}

// ---------------------------------------------------------------------------
// launch
// ---------------------------------------------------------------------------
extern "C" void kernel_launch(void* const* d_in, const int* in_sizes, int n_in,
                              void* d_out, int out_size) {
    const float* x        = (const float*)d_in[0];
    const float* ln_g     = (const float*)d_in[1];
    const float* ln_b     = (const float*)d_in[2];
    const float* W_hidden = (const float*)d_in[3];
    const float* b_hidden = (const float*)d_in[4];
    const float* W_qk     = (const float*)d_in[5];
    const float* b_qk     = (const float*)d_in[6];
    const float* os_gamma = (const float*)d_in[7];
    const float* os_beta  = (const float*)d_in[8];
    const float* W_out    = (const float*)d_in[9];
    const float* b_out    = (const float*)d_in[10];
    float* out = (float*)d_out;

    unsigned char* S = nullptr;
    cudaGetSymbolAddress((void**)&S, g_scr);
    bf16*  normed = (bf16*)(S + OFF_NORMED);
    bf16*  Wh     = (bf16*)(S + OFF_WH);
    bf16*  Wqk    = (bf16*)(S + OFF_WQK);
    bf16*  Wout   = (bf16*)(S + OFF_WOUT);
    bf16*  hbuf   = (bf16*)(S + OFF_HBUF);    // [8192][4096]: v | gate
    float* qkf    = (float*)(S + OFF_QKF);
    bf16*  heads  = (bf16*)(S + OFF_HEADS);
    bf16*  linkT  = (bf16*)(S + OFF_LINKT);
    bf16*  attn   = (bf16*)(S + OFF_ATTN);
    bf16*  quad   = (bf16*)(S + OFF_QUAD);
    float* lkvf   = (float*)(S + OFF_LKVF);
    bf16*  lkvb   = (bf16*)(S + OFF_LKVB);
    bf16*  comb   = (bf16*)(S + OFF_COMB);

    // weight conversions
    f2bf_kernel<<<(Dm * 2 * Hm / 4 + 255) / 256, 256>>>(W_hidden, Wh, Dm * 2 * Hm / 4);
    f2bf_kernel<<<(Dm * QKd / 4 + 255) / 256, 256>>>(W_qk, Wqk, Dm * QKd / 4);
    f2bf_kernel<<<(Hm * Dm / 4 + 255) / 256, 256>>>(W_out, Wout, Hm * Dm / 4);

    // LayerNorm -> bf16
    layernorm_kernel<<<ROWS, 256>>>(x, ln_g, ln_b, normed);

    // zero split-K accumulators
    cudaMemsetAsync(qkf,  0, (size_t)ROWS * QKd * sizeof(float), 0);
    cudaMemsetAsync(lkvf, 0, (size_t)Bsz * QKd * Hm * sizeof(float), 0);

    // 2) hidden: hbuf = silu(normed @ W_hidden + b_hidden)   [8192 x 4096 x 1024]
    gemm_bf16<EPI_SILU, 0><<<dim3(2 * Hm / BN, ROWS / BM, 1), 256, SMEM_BYTES>>>(
        normed, Wh, hbuf, Dm, 2 * Hm, 2 * Hm, Dm, 1, 0, 0, 0, 1.f,
        b_hidden, nullptr, 0, 0, nullptr, 0, 0, nullptr, 0);

    // 3) qk = normed @ W_qk  (split-K=4, fp32 atomics)       [8192 x 128 x 1024]
    gemm_bf16<EPI_ATOMIC, 0><<<dim3(1, ROWS / BM, 4), 256, SMEM_BYTES>>>(
        normed, Wqk, qkf, Dm, QKd, QKd, Dm / 4, 4, 0, 0, 0, 1.f,
        nullptr, nullptr, 0, 0, nullptr, 0, 0, nullptr, 0);

    // 4) OffsetScale + RoPE
    rope_kernel<<<ROWS, 256>>>(qkf, b_qk, os_gamma, os_beta, heads, linkT);

    // 5) attn = relu(QqKq^T / G)^2   per group               [256 x 256 x 128] x32
    gemm_bf16<EPI_RELU2, 1><<<dim3(2, 2, NGROUPS), 256, SMEM_BYTES>>>(
        heads + 0 * HEADSZ, heads + 2 * HEADSZ, attn, QKd, QKd, Gsz, QKd, 1,
        (long long)Gsz * QKd, (long long)Gsz * QKd, (long long)Gsz * Gsz, 1.f / Gsz,
        nullptr, nullptr, 0, 0, nullptr, 0, 0, nullptr, 0);

    // 6) quad = attn @ v   per group                          [256 x 2048 x 256] x32
    gemm_bf16<EPI_STOREB, 0><<<dim3(Hm / BN, 2, NGROUPS), 256, SMEM_BYTES>>>(
        attn, hbuf, quad, Gsz, 2 * Hm, Hm, Gsz, 1,
        (long long)Gsz * Gsz, (long long)Gsz * 2 * Hm, (long long)Gsz * Hm, 1.f,
        nullptr, nullptr, 0, 0, nullptr, 0, 0, nullptr, 0);

    // 7) lin_kv = (lin_k^T @ v) / N   per batch, split-K=4    [128 x 2048 x 2048] x4
    gemm_bf16<EPI_ATOMIC, 0><<<dim3(Hm / BN, 1, Bsz * 4), 256, SMEM_BYTES>>>(
        linkT, hbuf, lkvf, Nseq, 2 * Hm, Hm, Nseq / 4, 4,
        (long long)QKd * Nseq, (long long)Nseq * 2 * Hm, (long long)QKd * Hm, 1.f / Nseq,
        nullptr, nullptr, 0, 0, nullptr, 0, 0, nullptr, 0);
    f2bf_kernel<<<(Bsz * QKd * Hm / 4 + 255) / 256, 256>>>(lkvf, lkvb, Bsz * QKd * Hm / 4);

    // 8) comb = gate * (quad + lin_q @ lin_kv)  per batch     [2048 x 2048 x 128] x4
    gemm_bf16<EPI_COMBINE, 0><<<dim3(Hm / BN, Nseq / BM, Bsz), 256, SMEM_BYTES>>>(
        heads + 1 * HEADSZ, lkvb, comb, QKd, Hm, Hm, QKd, 1,
        (long long)Nseq * QKd, (long long)QKd * Hm, (long long)Nseq * Hm, 1.f,
        nullptr,
        hbuf + Hm, (long long)Nseq * 2 * Hm, 2 * Hm,    // gate
        quad,      (long long)Nseq * Hm,     Hm,        // quad_out
        nullptr, 0);

    // 9) out = comb @ W_out + b_out + x                       [8192 x 1024 x 2048]
    gemm_bf16<EPI_FINAL, 0><<<dim3(Dm / BN, ROWS / BM, 1), 256, SMEM_BYTES>>>(
        comb, Wout, out, Hm, Dm, Dm, Hm, 1, 0, 0, 0, 1.f,
        b_out, nullptr, 0, 0, nullptr, 0, 0, x, Dm);
}

// round 8
// speedup vs baseline: 6.7085x; 1.1705x over previous
#include <cuda_runtime.h>
#include <cuda_fp16.h>
#include <math.h>
#include <stdint.h>

// ---------------------------------------------------------------------------
// Problem constants
// ---------------------------------------------------------------------------
#define Bsz 4
#define Nseq 2048
#define Dm 1024
#define Hm 2048
#define QKd 128
#define Gsz 256
#define ROWS (Bsz * Nseq)          // 8192
#define NGROUPS (Bsz * (Nseq/Gsz)) // 32
#define HEADSZ ((long long)ROWS * QKd)

typedef __half fp16;

// ---------------------------------------------------------------------------
// Scratch (bytes)
// ---------------------------------------------------------------------------
#define OFF_NORMED 0ull                              // fp16 [8192][1024]  16MB
#define OFF_WH     (OFF_NORMED + 16777216ull)        // fp16 [1024][4096]   8MB
#define OFF_WQK    (OFF_WH     + 8388608ull)         // fp16 [1024][128]
#define OFF_WOUT   (OFF_WQK    + 262144ull)          // fp16 [2048][1024]   4MB
#define OFF_HBUF   (OFF_WOUT   + 4194304ull)         // fp16 [8192][4096]  64MB (v | gate)
#define OFF_QKF    (OFF_HBUF   + 67108864ull)        // f32  [8192][128]    4MB
#define OFF_HEADS  (OFF_QKF    + 4194304ull)         // fp16 [4][8192][128] 8MB
#define OFF_LINKT  (OFF_HEADS  + 8388608ull)         // fp16 [4][128][2048] 2MB
#define OFF_ATTN   (OFF_LINKT  + 2097152ull)         // fp16 [32][256][256] 4MB
#define OFF_QUAD   (OFF_ATTN   + 4194304ull)         // fp16 [8192][2048]  32MB
#define OFF_LKVF   (OFF_QUAD   + 33554432ull)        // f32  [4][128][2048] 4MB
#define OFF_LKVB   (OFF_LKVF   + 4194304ull)         // fp16 [4][128][2048] 2MB
#define OFF_COMB   (OFF_LKVB   + 2097152ull)         // fp16 [8192][2048]  32MB
#define SCR_BYTES  (OFF_COMB   + 33554432ull)

__device__ __align__(256) unsigned char g_scr[SCR_BYTES];

// ---------------------------------------------------------------------------
// PTX helpers
// ---------------------------------------------------------------------------
__device__ __forceinline__ uint32_t smem_u32(const void* p) {
    uint32_t a;
    asm("{ .reg .u64 t; cvta.to.shared.u64 t, %1; cvt.u32.u64 %0, t; }"
        : "=r"(a) : "l"(p));
    return a;
}
__device__ __forceinline__ void cpasync16(uint32_t s, const void* g) {
    asm volatile("cp.async.cg.shared.global [%0], [%1], 16;\n" :: "r"(s), "l"(g));
}
__device__ __forceinline__ void cp_commit() { asm volatile("cp.async.commit_group;\n"); }

__device__ __forceinline__ void ldsm4(uint32_t r[4], uint32_t a) {
    asm volatile("ldmatrix.sync.aligned.m8n8.x4.shared.b16 {%0,%1,%2,%3}, [%4];\n"
                 : "=r"(r[0]), "=r"(r[1]), "=r"(r[2]), "=r"(r[3]) : "r"(a));
}
__device__ __forceinline__ void ldsm4t(uint32_t r[4], uint32_t a) {
    asm volatile("ldmatrix.sync.aligned.m8n8.x4.trans.shared.b16 {%0,%1,%2,%3}, [%4];\n"
                 : "=r"(r[0]), "=r"(r[1]), "=r"(r[2]), "=r"(r[3]) : "r"(a));
}
// fp16 inputs, fp16 accumulate (2x rate on quarter-rate legacy datapath)
__device__ __forceinline__ void mma16816h(uint32_t c[2], const uint32_t a[4],
                                          uint32_t b0, uint32_t b1) {
    asm volatile("mma.sync.aligned.m16n8k16.row.col.f16.f16.f16.f16 "
                 "{%0,%1}, {%2,%3,%4,%5}, {%6,%7}, {%0,%1};\n"
                 : "+r"(c[0]), "+r"(c[1])
                 : "r"(a[0]), "r"(a[1]), "r"(a[2]), "r"(a[3]), "r"(b0), "r"(b1));
}

// Conflict-free swizzles (byte offsets, 2B elements).
__device__ __forceinline__ uint32_t swz64(int r, int cb) {
    return (uint32_t)(r * 64 + ((((cb >> 4) ^ ((r >> 1) & 3)) << 4) | (cb & 15)));
}
__device__ __forceinline__ uint32_t swz256(int k, int nb) {
    int ch = nb >> 4;
    ch = (ch & 8) | ((ch ^ k) & 7);
    return (uint32_t)(k * 256 + (ch << 4) + (nb & 15));
}

__device__ __forceinline__ uint32_t pkh2(float a, float b) {
    __half2 t = __floats2half2_rn(a, b);
    return *(uint32_t*)&t;
}

// ---------------------------------------------------------------------------
// LayerNorm (fp32 in, fp16 out)
// ---------------------------------------------------------------------------
__global__ void layernorm_kernel(const float* __restrict__ x,
                                 const float* __restrict__ g,
                                 const float* __restrict__ b,
                                 fp16* __restrict__ out) {
    long long row = blockIdx.x;
    int t = threadIdx.x;
    float4 v = ((const float4*)(x + row * Dm))[t];
    float s  = v.x + v.y + v.z + v.w;
    float sq = v.x*v.x + v.y*v.y + v.z*v.z + v.w*v.w;
    #pragma unroll
    for (int o = 16; o; o >>= 1) {
        s  += __shfl_xor_sync(0xffffffffu, s,  o);
        sq += __shfl_xor_sync(0xffffffffu, sq, o);
    }
    __shared__ float ss[8], sqs[8];
    if ((t & 31) == 0) { ss[t >> 5] = s; sqs[t >> 5] = sq; }
    __syncthreads();
    if (t < 32) {
        float a  = (t < 8) ? ss[t]  : 0.f;
        float a2 = (t < 8) ? sqs[t] : 0.f;
        #pragma unroll
        for (int o = 4; o; o >>= 1) {
            a  += __shfl_xor_sync(0xffffffffu, a,  o);
            a2 += __shfl_xor_sync(0xffffffffu, a2, o);
        }
        if (t == 0) { ss[0] = a; sqs[0] = a2; }
    }
    __syncthreads();
    float mean = ss[0] * (1.f / Dm);
    float var  = sqs[0] * (1.f / Dm) - mean * mean;
    float inv  = rsqrtf(var + 1e-5f);
    float4 gg = ((const float4*)g)[t];
    float4 bb = ((const float4*)b)[t];
    __half2* op = (__half2*)(out + row * Dm);
    op[2*t]   = __floats2half2_rn((v.x - mean) * inv * gg.x + bb.x,
                                  (v.y - mean) * inv * gg.y + bb.y);
    op[2*t+1] = __floats2half2_rn((v.z - mean) * inv * gg.z + bb.z,
                                  (v.w - mean) * inv * gg.w + bb.w);
}

// ---------------------------------------------------------------------------
// fp32 -> fp16 (vectorized by 4)
// ---------------------------------------------------------------------------
__global__ void f2h_kernel(const float* __restrict__ in, fp16* __restrict__ out, int n4) {
    int i = blockIdx.x * blockDim.x + threadIdx.x;
    if (i < n4) {
        float4 v = ((const float4*)in)[i];
        ((__half2*)out)[2*i]   = __floats2half2_rn(v.x, v.y);
        ((__half2*)out)[2*i+1] = __floats2half2_rn(v.z, v.w);
    }
}

// ---------------------------------------------------------------------------
// OffsetScale + RoPE (fp32 math; fp16 out). Also writes lin_k transposed.
// heads: [4][8192][128]; linkT: [4 batches][128][2048]
// ---------------------------------------------------------------------------
__global__ void rope_kernel(const float* __restrict__ qk,
                            const float* __restrict__ b_qk,
                            const float* __restrict__ gamma,
                            const float* __restrict__ beta,
                            fp16* __restrict__ heads,
                            fp16* __restrict__ linkT) {
    int row = blockIdx.x;
    int h = threadIdx.x >> 6;
    int j = threadIdx.x & 63;
    __shared__ float s[QKd];
    __shared__ float sc[64], ss_[64];
    if (threadIdx.x < QKd) {
        float z = qk[(long long)row * QKd + threadIdx.x] + b_qk[threadIdx.x];
        s[threadIdx.x] = z / (1.f + expf(-z));
    }
    if (threadIdx.x < 64) {
        int pos = row & (Nseq - 1);
        float invf = powf(10000.0f, (float)threadIdx.x * (1.0f / 64.0f));
        float th = (float)pos * invf;
        sc[threadIdx.x]  = cosf(th);
        ss_[threadIdx.x] = sinf(th);
    }
    __syncthreads();
    float a1 = s[j]      * gamma[h * QKd + j]      + beta[h * QKd + j];
    float a2 = s[j + 64] * gamma[h * QKd + j + 64] + beta[h * QKd + j + 64];
    float cs = sc[j], sn = ss_[j];
    float r1 = a1 * cs - a2 * sn;
    float r2 = a2 * cs + a1 * sn;
    long long base = ((long long)h * ROWS + row) * QKd;
    heads[base + j]      = __float2half_rn(r1);
    heads[base + j + 64] = __float2half_rn(r2);
    if (h == 3) {
        int batch = row >> 11;
        int pos   = row & (Nseq - 1);
        long long tb = (long long)batch * QKd * Nseq;
        linkT[tb + (long long)j * Nseq + pos]        = __float2half_rn(r1);
        linkT[tb + (long long)(j + 64) * Nseq + pos] = __float2half_rn(r2);
    }
}

// ---------------------------------------------------------------------------
// fp16 tensor-core GEMM: 128x128x32 block, 8 warps (4x2), 32x64 warp tiles.
// fp16 accumulate. 3-stage cp.async pipeline, XOR-swizzled smem.
// A row-major [M][K]. BL=0: B stored [K][N]; BL=1: B stored [N][K].
// ---------------------------------------------------------------------------
#define BM 128
#define BN 128
#define BK 32
#define STAGES 3
#define SMEM_BYTES (STAGES * 2 * 8192)     // 48KB

#define EPI_SILU    0
#define EPI_RELU2   1
#define EPI_STOREB  2
#define EPI_ATOMIC  3
#define EPI_COMBINE 4
#define EPI_FINAL   5

template<int EPI, int BL>
__global__ __launch_bounds__(256)
void gemm_fp16(const fp16* __restrict__ A, const fp16* __restrict__ B,
               void* __restrict__ Cv,
               int lda, int ldb, int ldc,
               int kchunk, int nk,
               long long sA, long long sB, long long sC,
               float scale,
               const float* __restrict__ bias,
               const fp16* __restrict__ ep0, long long s0, int ld0,
               const fp16* __restrict__ ep1, long long s1, int ld1,
               const float* __restrict__ xres, int ldx) {
    extern __shared__ unsigned char smem[];
    const uint32_t aSm = smem_u32(smem);                    // STAGES x 8KB
    const uint32_t bSm = aSm + STAGES * 8192;               // STAGES x 8KB

    const int tid = threadIdx.x;
    const int z = blockIdx.z;
    const int batch = z / nk, kc = z - batch * nk;
    A += batch * sA + (long long)kc * kchunk;
    if (BL == 0) B += batch * sB + (long long)kc * kchunk * ldb;
    else         B += batch * sB + (long long)kc * kchunk;
    const int m0 = blockIdx.y * BM, n0 = blockIdx.x * BN;

    const int lane = tid & 31, wid = tid >> 5;
    const int wm = wid & 3, wn = wid >> 2;

    // fp16 accumulators: [mi][nb][r2] = half2 (col, col+1) at row base + r2*8
    uint32_t acc[2][8][2];
    #pragma unroll
    for (int i = 0; i < 2; i++)
        #pragma unroll
        for (int j = 0; j < 8; j++) { acc[i][j][0] = 0u; acc[i][j][1] = 0u; }

    const int iters = kchunk / BK;

    const int ar  = tid >> 2, acb = (tid & 3) * 16;
    const int b0k = tid >> 4, b0n = (tid & 15) * 16;

    auto load_stage = [&](int st, int k0) {
        const uint32_t aDst = aSm + st * 8192;
        const fp16* ga = A + (long long)(m0 + ar) * lda + k0 + (acb >> 1);
        cpasync16(aDst + swz64(ar, acb), ga);
        cpasync16(aDst + swz64(ar + 64, acb), ga + 64ll * lda);
        const uint32_t bDst = bSm + st * 8192;
        if (BL == 0) {
            const fp16* gb = B + (long long)(k0 + b0k) * ldb + n0 + (b0n >> 1);
            cpasync16(bDst + swz256(b0k, b0n), gb);
            cpasync16(bDst + swz256(b0k + 16, b0n), gb + 16ll * ldb);
        } else {
            const fp16* gb = B + (long long)(n0 + ar) * ldb + k0 + (acb >> 1);
            cpasync16(bDst + swz64(ar, acb), gb);
            cpasync16(bDst + swz64(ar + 64, acb), gb + 64ll * ldb);
        }
        cp_commit();
    };

    load_stage(0, 0);
    if (iters > 1) load_stage(1, BK);

    for (int it = 0; it < iters; ++it) {
        if (it + 1 < iters) asm volatile("cp.async.wait_group 1;\n" ::: "memory");
        else                asm volatile("cp.async.wait_group 0;\n" ::: "memory");
        __syncthreads();
        if (it + 2 < iters) load_stage((it + 2) % STAGES, (it + 2) * BK);

        const int st = it % STAGES;
        const uint32_t aB = aSm + st * 8192;
        const uint32_t bB = bSm + st * 8192;
        #pragma unroll
        for (int ks = 0; ks < 2; ++ks) {
            uint32_t a[2][4];
            #pragma unroll
            for (int mi = 0; mi < 2; ++mi) {
                int r = wm * 32 + mi * 16 + (lane & 15);
                ldsm4(a[mi], aB + swz64(r, ks * 32 + (lane >> 4) * 16));
            }
            uint32_t b[4][4];
            #pragma unroll
            for (int nb = 0; nb < 4; ++nb) {
                if (BL == 0) {
                    int k = ks * 16 + (lane & 15);
                    int nbyte = (wn * 64 + nb * 16 + (lane >> 4) * 8) * 2;
                    ldsm4t(b[nb], bB + swz256(k, nbyte));
                } else {
                    int r = wn * 64 + nb * 16 + (lane & 7) + (lane >> 4) * 8;
                    int cb = (ks * 16 + ((lane >> 3) & 1) * 8) * 2;
                    ldsm4(b[nb], bB + swz64(r, cb));
                }
            }
            #pragma unroll
            for (int mi = 0; mi < 2; ++mi)
                #pragma unroll
                for (int nb = 0; nb < 4; ++nb) {
                    mma16816h(acc[mi][2 * nb],     a[mi], b[nb][0], b[nb][1]);
                    mma16816h(acc[mi][2 * nb + 1], a[mi], b[nb][2], b[nb][3]);
                }
        }
    }

    // epilogue
    #pragma unroll
    for (int mi = 0; mi < 2; ++mi)
        #pragma unroll
        for (int r2 = 0; r2 < 2; ++r2) {
            int row = m0 + wm * 32 + mi * 16 + (lane >> 2) + r2 * 8;
            #pragma unroll
            for (int nb = 0; nb < 8; ++nb) {
                int col = n0 + wn * 64 + nb * 8 + (lane & 3) * 2;
                float2 vf = __half22float2(*(__half2*)&acc[mi][nb][r2]);
                float v0 = vf.x * scale;
                float v1 = vf.y * scale;
                long long idx = batch * sC + (long long)row * ldc + col;
                if (EPI == EPI_SILU) {
                    v0 += bias[col]; v1 += bias[col + 1];
                    v0 = v0 / (1.f + expf(-v0));
                    v1 = v1 / (1.f + expf(-v1));
                    *(__half2*)((fp16*)Cv + idx) = __floats2half2_rn(v0, v1);
                } else if (EPI == EPI_RELU2) {
                    float r0 = v0 > 0.f ? v0 : 0.f;
                    float r1 = v1 > 0.f ? v1 : 0.f;
                    *(__half2*)((fp16*)Cv + idx) = __floats2half2_rn(r0 * r0, r1 * r1);
                } else if (EPI == EPI_STOREB) {
                    *(__half2*)((fp16*)Cv + idx) = __floats2half2_rn(v0, v1);
                } else if (EPI == EPI_ATOMIC) {
                    atomicAdd((float*)Cv + idx, v0);
                    atomicAdd((float*)Cv + idx + 1, v1);
                } else if (EPI == EPI_COMBINE) {
                    __half2 g2 = *(const __half2*)(ep0 + batch * s0 + (long long)row * ld0 + col);
                    __half2 q2 = *(const __half2*)(ep1 + batch * s1 + (long long)row * ld1 + col);
                    float2 gf = __half22float2(g2);
                    float2 qf = __half22float2(q2);
                    float o0 = gf.x * (qf.x + v0);
                    float o1 = gf.y * (qf.y + v1);
                    *(__half2*)((fp16*)Cv + idx) = __floats2half2_rn(o0, o1);
                } else if (EPI == EPI_FINAL) {
                    v0 += bias[col] + xres[(long long)row * ldx + col];
                    v1 += bias[col + 1] + xres[(long long)row * ldx + col + 1];
                    *(float2*)((float*)Cv + idx) = make_float2(v0, v1);
                }
            }
        }
}

// ---------------------------------------------------------------------------
// launch
// ---------------------------------------------------------------------------
extern "C" void kernel_launch(void* const* d_in, const int* in_sizes, int n_in,
                              void* d_out, int out_size) {
    const float* x        = (const float*)d_in[0];
    const float* ln_g     = (const float*)d_in[1];
    const float* ln_b     = (const float*)d_in[2];
    const float* W_hidden = (const float*)d_in[3];
    const float* b_hidden = (const float*)d_in[4];
    const float* W_qk     = (const float*)d_in[5];
    const float* b_qk     = (const float*)d_in[6];
    const float* os_gamma = (const float*)d_in[7];
    const float* os_beta  = (const float*)d_in[8];
    const float* W_out    = (const float*)d_in[9];
    const float* b_out    = (const float*)d_in[10];
    float* out = (float*)d_out;

    unsigned char* S = nullptr;
    cudaGetSymbolAddress((void**)&S, g_scr);
    fp16*  normed = (fp16*)(S + OFF_NORMED);
    fp16*  Wh     = (fp16*)(S + OFF_WH);
    fp16*  Wqk    = (fp16*)(S + OFF_WQK);
    fp16*  Wout   = (fp16*)(S + OFF_WOUT);
    fp16*  hbuf   = (fp16*)(S + OFF_HBUF);    // [8192][4096]: v | gate
    float* qkf    = (float*)(S + OFF_QKF);
    fp16*  heads  = (fp16*)(S + OFF_HEADS);
    fp16*  linkT  = (fp16*)(S + OFF_LINKT);
    fp16*  attn   = (fp16*)(S + OFF_ATTN);
    fp16*  quad   = (fp16*)(S + OFF_QUAD);
    float* lkvf   = (float*)(S + OFF_LKVF);
    fp16*  lkvb   = (fp16*)(S + OFF_LKVB);
    fp16*  comb   = (fp16*)(S + OFF_COMB);

    // weight conversions
    f2h_kernel<<<(Dm * 2 * Hm / 4 + 255) / 256, 256>>>(W_hidden, Wh, Dm * 2 * Hm / 4);
    f2h_kernel<<<(Dm * QKd / 4 + 255) / 256, 256>>>(W_qk, Wqk, Dm * QKd / 4);
    f2h_kernel<<<(Hm * Dm / 4 + 255) / 256, 256>>>(W_out, Wout, Hm * Dm / 4);

    // LayerNorm -> fp16
    layernorm_kernel<<<ROWS, 256>>>(x, ln_g, ln_b, normed);

    // zero split-K accumulators
    cudaMemsetAsync(qkf,  0, (size_t)ROWS * QKd * sizeof(float), 0);
    cudaMemsetAsync(lkvf, 0, (size_t)Bsz * QKd * Hm * sizeof(float), 0);

    // 2) hidden: hbuf = silu(normed @ W_hidden + b_hidden)   [8192 x 4096 x 1024]
    gemm_fp16<EPI_SILU, 0><<<dim3(2 * Hm / BN, ROWS / BM, 1), 256, SMEM_BYTES>>>(
        normed, Wh, hbuf, Dm, 2 * Hm, 2 * Hm, Dm, 1, 0, 0, 0, 1.f,
        b_hidden, nullptr, 0, 0, nullptr, 0, 0, nullptr, 0);

    // 3) qk = normed @ W_qk  (split-K=4, fp32 atomics)       [8192 x 128 x 1024]
    gemm_fp16<EPI_ATOMIC, 0><<<dim3(1, ROWS / BM, 4), 256, SMEM_BYTES>>>(
        normed, Wqk, qkf, Dm, QKd, QKd, Dm / 4, 4, 0, 0, 0, 1.f,
        nullptr, nullptr, 0, 0, nullptr, 0, 0, nullptr, 0);

    // 4) OffsetScale + RoPE
    rope_kernel<<<ROWS, 256>>>(qkf, b_qk, os_gamma, os_beta, heads, linkT);

    // 5) attn = relu(QqKq^T / G)^2   per group               [256 x 256 x 128] x32
    gemm_fp16<EPI_RELU2, 1><<<dim3(2, 2, NGROUPS), 256, SMEM_BYTES>>>(
        heads + 0 * HEADSZ, heads + 2 * HEADSZ, attn, QKd, QKd, Gsz, QKd, 1,
        (long long)Gsz * QKd, (long long)Gsz * QKd, (long long)Gsz * Gsz, 1.f / Gsz,
        nullptr, nullptr, 0, 0, nullptr, 0, 0, nullptr, 0);

    // 6) quad = attn @ v   per group                          [256 x 2048 x 256] x32
    gemm_fp16<EPI_STOREB, 0><<<dim3(Hm / BN, 2, NGROUPS), 256, SMEM_BYTES>>>(
        attn, hbuf, quad, Gsz, 2 * Hm, Hm, Gsz, 1,
        (long long)Gsz * Gsz, (long long)Gsz * 2 * Hm, (long long)Gsz * Hm, 1.f,
        nullptr, nullptr, 0, 0, nullptr, 0, 0, nullptr, 0);

    // 7) lin_kv = (lin_k^T @ v) / N   per batch, split-K=4    [128 x 2048 x 2048] x4
    gemm_fp16<EPI_ATOMIC, 0><<<dim3(Hm / BN, 1, Bsz * 4), 256, SMEM_BYTES>>>(
        linkT, hbuf, lkvf, Nseq, 2 * Hm, Hm, Nseq / 4, 4,
        (long long)QKd * Nseq, (long long)Nseq * 2 * Hm, (long long)QKd * Hm, 1.f / Nseq,
        nullptr, nullptr, 0, 0, nullptr, 0, 0, nullptr, 0);
    f2h_kernel<<<(Bsz * QKd * Hm / 4 + 255) / 256, 256>>>(lkvf, lkvb, Bsz * QKd * Hm / 4);

    // 8) comb = gate * (quad + lin_q @ lin_kv)  per batch     [2048 x 2048 x 128] x4
    gemm_fp16<EPI_COMBINE, 0><<<dim3(Hm / BN, Nseq / BM, Bsz), 256, SMEM_BYTES>>>(
        heads + 1 * HEADSZ, lkvb, comb, QKd, Hm, Hm, QKd, 1,
        (long long)Nseq * QKd, (long long)QKd * Hm, (long long)Nseq * Hm, 1.f,
        nullptr,
        hbuf + Hm, (long long)Nseq * 2 * Hm, 2 * Hm,    // gate
        quad,      (long long)Nseq * Hm,     Hm,        // quad_out
        nullptr, 0);

    // 9) out = comb @ W_out + b_out + x                       [8192 x 1024 x 2048]
    gemm_fp16<EPI_FINAL, 0><<<dim3(Dm / BN, ROWS / BM, 1), 256, SMEM_BYTES>>>(
        comb, Wout, out, Hm, Dm, Dm, Hm, 1, 0, 0, 0, 1.f,
        b_out, nullptr, 0, 0, nullptr, 0, 0, x, Dm);
}